// round 15
// baseline (speedup 1.0000x reference)
#include <cuda_runtime.h>
#include <stdint.h>

// Fixed problem shape
#define VV        128000          // floats per row
#define ROW_BYTES (VV * 4)        // 512000
#define ROWS_MAX  256
#define CAP       512             // candidates/row (observed ~173; fallback guards)
#define KTOP      50
#define THRESH    3.0f

// Quarter-row jobs streamed by a balanced single-wave grid
#define NTH        256
#define GRID_CTAS  296            // 148 SMs * 2 CTAs -> exactly one wave
#define Q_BYTES    128000         // quarter row
#define Q_FLOATS   32000
#define TILE_BYTES 25600          // 6400 floats, 1600 float4
#define TILE_F     6400
#define TILE_F4    1600
#define TPQ        5              // tiles per quarter (5*25600 = 128000)
#define NBUF       4              // 102.4 KB ring -> 2 CTAs/SM

#define BUF_TOTAL  (NBUF * TILE_BYTES)   // 102400
#define MBAR_OFF   BUF_TOTAL
#define SMEM_TOTAL (BUF_TOTAL + 64)

// Per-row global scratch (zero-init at load; re-armed by the selection CTA).
__device__ int   g_cnt[ROWS_MAX];
__device__ int   g_done[ROWS_MAX];
__device__ float g_vals[ROWS_MAX][CAP];
__device__ int   g_idx[ROWS_MAX][CAP];

// ---------------------------------------------------------------------------
// JAX threefry2x32, partitionable mode. key = jax.random.key(42) -> (0, 42).
// counter = (hi32(n)=0, lo32(n)=n); 32-bit output = lane0 ^ lane1.
// ---------------------------------------------------------------------------
__device__ __forceinline__ uint32_t rotl32(uint32_t x, int r) {
    return (x << r) | (x >> (32 - r));
}

__device__ __forceinline__ uint32_t jax_bits_part(uint32_t n) {
    const uint32_t ks0 = 0u;
    const uint32_t ks1 = 42u;
    const uint32_t ks2 = 0x1BD11BDAu ^ 0u ^ 42u;   // 0x1BD11BF0
    uint32_t x0 = 0u + ks0;
    uint32_t x1 = n  + ks1;
#define TF_RND(r) { x0 += x1; x1 = rotl32(x1, (r)); x1 ^= x0; }
    TF_RND(13) TF_RND(15) TF_RND(26) TF_RND(6)   x0 += ks1; x1 += ks2 + 1u;
    TF_RND(17) TF_RND(29) TF_RND(16) TF_RND(24)  x0 += ks2; x1 += ks0 + 2u;
    TF_RND(13) TF_RND(15) TF_RND(26) TF_RND(6)   x0 += ks0; x1 += ks1 + 3u;
    TF_RND(17) TF_RND(29) TF_RND(16) TF_RND(24)  x0 += ks1; x1 += ks2 + 4u;
    TF_RND(13) TF_RND(15) TF_RND(26) TF_RND(6)   x0 += ks2; x1 += ks0 + 5u;
#undef TF_RND
    return x0 ^ x1;
}

__device__ __forceinline__ float jax_gumbel(uint32_t n) {
    const float TINY = 1.17549435e-38f;
    uint32_t bits = jax_bits_part(n);
    float u01 = __uint_as_float((bits >> 9) | 0x3f800000u) - 1.0f;
    float u = fmaxf(TINY, u01 + TINY);
    return -logf(-logf(u));
}

__device__ __forceinline__ uint32_t f2s(float f) {
    uint32_t u = __float_as_uint(f);
    return u ^ (uint32_t)(((int32_t)u >> 31) | (int32_t)0x80000000);
}

// ---------------------------------------------------------------------------
// PTX helpers (bulk-copy pipeline)
// ---------------------------------------------------------------------------
__device__ __forceinline__ uint32_t smem_u32(const void* p) {
    uint32_t a;
    asm("{ .reg .u64 t; cvta.to.shared.u64 t, %1; cvt.u32.u64 %0, t; }"
        : "=r"(a) : "l"(p));
    return a;
}

__device__ __forceinline__ void mbar_init(uint32_t mbar, uint32_t count) {
    asm volatile("mbarrier.init.shared.b64 [%0], %1;" :: "r"(mbar), "r"(count)
                 : "memory");
}

__device__ __forceinline__ void mbar_expect_tx(uint32_t mbar, uint32_t bytes) {
    asm volatile("mbarrier.arrive.expect_tx.shared.b64 _, [%0], %1;"
                 :: "r"(mbar), "r"(bytes) : "memory");
}

__device__ __forceinline__ void bulk_g2s(uint32_t smem_dst, const void* gmem_src,
                                         uint32_t bytes, uint32_t mbar) {
    asm volatile(
        "cp.async.bulk.shared::cta.global.mbarrier::complete_tx::bytes "
        "[%0], [%1], %2, [%3];"
        :: "r"(smem_dst), "l"(gmem_src), "r"(bytes), "r"(mbar) : "memory");
}

__device__ __forceinline__ void mbar_wait(uint32_t mbar, uint32_t parity) {
    asm volatile(
        "{\n\t"
        ".reg .pred P;\n\t"
        "WAIT_%=:\n\t"
        "mbarrier.try_wait.parity.acquire.cta.shared::cta.b64 P, [%0], %1, 0x989680;\n\t"
        "@P bra.uni DONE_%=;\n\t"
        "bra.uni WAIT_%=;\n\t"
        "DONE_%=:\n\t"
        "}"
        :: "r"(mbar), "r"(parity) : "memory");
}

// ---------------------------------------------------------------------------
// 296 CTAs (one full wave, 2 per SM). CTA c streams quarter-row jobs
// q = c, c+296, c+592, c+888 as ONE continuous tile sequence through a
// 4-deep cp.async.bulk ring (ring never drains across job boundaries).
// Candidates -> per-row global lists; the 4th finisher of each row runs
// selection + gumbel sampling inline and re-arms the row counters.
// ---------------------------------------------------------------------------
__global__ __launch_bounds__(NTH)
void sampler_balanced_kernel(const float* __restrict__ logits,
                             const float* __restrict__ temps,
                             float*       __restrict__ out,
                             int          rows)
{
    extern __shared__ __align__(1024) char smem[];
    __shared__ float s_val[CAP];
    __shared__ int   s_idx[CAP];
    __shared__ int   s_cnt;
    __shared__ float s_kth;
    __shared__ int   s_last;
    __shared__ unsigned long long s_best;

    const int c    = blockIdx.x;
    const int tid  = threadIdx.x;
    const int k    = KTOP;
    const int NQ   = rows * 4;                 // 1024 quarter jobs
    const char* __restrict__ gbase = reinterpret_cast<const char*>(logits);

    // Job count for this CTA (stride GRID_CTAS over NQ jobs).
    int njobs = 0;
    for (int q = c; q < NQ; q += GRID_CTAS) ++njobs;
    const int ntiles = njobs * TPQ;
    if (ntiles == 0) return;

    const uint32_t smem_base = smem_u32(smem);
    const uint32_t mbar0     = smem_base + MBAR_OFF;

    if (tid == 0) {
        #pragma unroll
        for (int b = 0; b < NBUF; ++b) mbar_init(mbar0 + 8 * b, 1);
    }
    __syncthreads();

    // Tile ti -> gmem byte offset (quarters may belong to different rows).
    auto tile_goff = [&](int ti) -> size_t {
        int job = ti / TPQ;
        int q   = c + job * GRID_CTAS;
        int row = q >> 2, seg = q & 3;
        return (size_t)row * ROW_BYTES + (size_t)seg * Q_BYTES
             + (size_t)(ti % TPQ) * TILE_BYTES;
    };

    // Prime the ring: tiles 0..min(NBUF,ntiles)-1.
    if (tid == 0) {
        for (int b = 0; b < NBUF && b < ntiles; ++b) {
            mbar_expect_tx(mbar0 + 8 * b, TILE_BYTES);
            bulk_g2s(smem_base + b * TILE_BYTES, gbase + tile_goff(b),
                     TILE_BYTES, mbar0 + 8 * b);
        }
    }

    // ---------------- continuous streaming scan ----------------
    for (int ti = 0; ti < ntiles; ++ti) {
        const int job = ti / TPQ;
        const int q   = c + job * GRID_CTAS;
        const int row = q >> 2, seg = q & 3;
        const int col0 = seg * Q_FLOATS + (ti % TPQ) * TILE_F;

        const int b = ti % NBUF;
        mbar_wait(mbar0 + 8 * b, (ti / NBUF) & 1);

        const float4* __restrict__ tb =
            reinterpret_cast<const float4*>(smem + b * TILE_BYTES);
        #pragma unroll 2
        for (int i = tid; i < TILE_F4; i += NTH) {
            float4 v = tb[i];
            float m = fmaxf(fmaxf(v.x, v.y), fmaxf(v.z, v.w));
            if (m >= THRESH) {     // rare (~0.5% of float4 groups)
                float xs[4] = {v.x, v.y, v.z, v.w};
                #pragma unroll
                for (int e = 0; e < 4; ++e) {
                    if (xs[e] >= THRESH) {
                        int p = atomicAdd(&g_cnt[row], 1);
                        if (p < CAP) {
                            g_vals[row][p] = xs[e];
                            g_idx[row][p]  = col0 + i * 4 + e;
                        }
                    }
                }
            }
        }
        __syncthreads();           // CTA done reading buffer b

        const int nt2 = ti + NBUF; // refill this buffer with a later tile
        if (nt2 < ntiles && tid == 0) {
            mbar_expect_tx(mbar0 + 8 * b, TILE_BYTES);
            bulk_g2s(smem_base + b * TILE_BYTES, gbase + tile_goff(nt2),
                     TILE_BYTES, mbar0 + 8 * b);
        }

        // ---------------- job boundary: ticket + maybe selection ----------
        if ((ti % TPQ) == TPQ - 1) {
            __threadfence();       // publish this quarter's candidate stores
            __syncthreads();
            if (tid == 0) s_last = (atomicAdd(&g_done[row], 1) == 3);
            __syncthreads();
            if (s_last) {
                __threadfence();   // acquire: all quarters' stores visible

                // -------- selection + sampling for this row --------
                const float temp = temps[row];
                if (tid == 0) {
                    s_best = 0ull; s_kth = __int_as_float(0xFF800000);
                }
                __syncthreads();

                int cnt = g_cnt[row];

                if (cnt >= k && cnt <= CAP) {
                    for (int i = tid; i < cnt; i += NTH) {
                        s_val[i] = g_vals[row][i];
                        s_idx[i] = g_idx[row][i];
                    }
                    __syncthreads();
                } else {
                    // Fallback: bisection rescan of the full row.
                    const float4* __restrict__ rowp =
                        reinterpret_cast<const float4*>(logits + (size_t)row * VV);
                    if (tid == 0) s_cnt = 0;
                    __syncthreads();
                    float Tlo = -3.0e38f, Thi = 3.0e38f, T = THRESH;
                    int cc = cnt;
                    for (int attempt = 0; attempt < 48; ++attempt) {
                        if (cc < k) { Thi = T; T = (Tlo < -1.0e38f) ? (T - 2.0f) : 0.5f * (Tlo + Thi); }
                        else        { Tlo = T; T = (Thi >  1.0e38f) ? (T + 2.0f) : 0.5f * (Tlo + Thi); }
                        __syncthreads();
                        if (tid == 0) s_cnt = 0;
                        __syncthreads();
                        for (int i = tid; i < VV / 4; i += NTH) {
                            float4 w = rowp[i];
                            float m = fmaxf(fmaxf(w.x, w.y), fmaxf(w.z, w.w));
                            if (m >= T) {
                                float xs[4] = {w.x, w.y, w.z, w.w};
                                #pragma unroll
                                for (int e = 0; e < 4; ++e) {
                                    if (xs[e] >= T) {
                                        int p = atomicAdd(&s_cnt, 1);
                                        if (p < CAP) { s_val[p] = xs[e]; s_idx[p] = i * 4 + e; }
                                    }
                                }
                            }
                        }
                        __syncthreads();
                        cc = s_cnt;
                        if (cc >= k && cc <= CAP) break;
                    }
                    cnt = min(cc, CAP);
                }

                // Exact temperature scaling (bit-matches reference's division).
                for (int i = tid; i < cnt; i += NTH)
                    s_val[i] = __fdiv_rn(s_val[i], temp);
                __syncthreads();

                // k-th largest among candidates (duplicate-aware rank count).
                for (int i = tid; i < cnt; i += NTH) {
                    float vv = s_val[i];
                    int cg = 0, ce = 0;
                    for (int j = 0; j < cnt; ++j) {
                        float u = s_val[j];
                        cg += (u > vv);
                        ce += (u == vv);
                    }
                    if (cg < k && cg + ce >= k) s_kth = vv;
                }
                __syncthreads();
                float kv = s_kth;

                // Gumbel-perturbed argmax; first-index tie-break.
                for (int i = tid; i < cnt; i += NTH) {
                    float vv = s_val[i];
                    if (vv >= kv) {
                        int col = s_idx[i];
                        uint32_t n = (uint32_t)row * (uint32_t)VV + (uint32_t)col;
                        float tot = vv + jax_gumbel(n);
                        unsigned long long pack =
                            ((unsigned long long)f2s(tot) << 32) |
                            (unsigned long long)(0xFFFFFFFFu - (uint32_t)col);
                        atomicMax(&s_best, pack);
                    }
                }
                __syncthreads();

                if (tid == 0) {
                    int win = (int)(0xFFFFFFFFu - (uint32_t)(s_best & 0xFFFFFFFFull));
                    out[row] = (float)win;   // harness output dtype is float32
                    g_cnt[row]  = 0;         // re-arm for next graph replay
                    g_done[row] = 0;
                }
                __syncthreads();
            }
        }
    }
}

extern "C" void kernel_launch(void* const* d_in, const int* in_sizes, int n_in,
                              void* d_out, int out_size)
{
    const float* logits = (const float*)d_in[0];
    const float* temps  = (const float*)d_in[1];
    float* out = (float*)d_out;

    int rows = (n_in >= 2 && in_sizes[1] > 0) ? in_sizes[1] : ROWS_MAX;  // 256

    cudaFuncSetAttribute(sampler_balanced_kernel,
                         cudaFuncAttributeMaxDynamicSharedMemorySize, SMEM_TOTAL);
    sampler_balanced_kernel<<<GRID_CTAS, NTH, SMEM_TOTAL>>>(logits, temps, out, rows);
}

// round 16
// speedup vs baseline: 2.3685x; 2.3685x over previous
#include <cuda_runtime.h>
#include <stdint.h>

// Fixed problem shape
#define VV        128000          // floats per row
#define ROW_BYTES (VV * 4)        // 512000
#define ROWS_MAX  256
#define CAP       512             // candidates/row (observed ~173; fallback guards)
#define KTOP      50
#define THRESH    3.0f

#define NTH        512
#define TILE_BYTES 25600          // 6400 floats, 1600 float4
#define TILE_F     6400
#define TILE_F4    1600
#define NT         20             // 20 * 25600 = 512000 = ROW_BYTES
#define NBUF       4
#define NSUB       4              // parallel sub-copies per tile fill
#define SUB_BYTES  (TILE_BYTES / NSUB)   // 6400

// L2 residency: first PERSIST_NT tiles evict_last, rest evict_first.
#define PERSIST_NT 18

#define BUF_TOTAL  (NBUF * TILE_BYTES)   // 102400
#define MBAR_OFF   BUF_TOTAL
#define SMEM_TOTAL (BUF_TOTAL + 64)

// ---------------------------------------------------------------------------
// JAX threefry2x32, partitionable mode. key = jax.random.key(42) -> (0, 42).
// counter = (hi32(n)=0, lo32(n)=n); 32-bit output = lane0 ^ lane1.
// ---------------------------------------------------------------------------
__device__ __forceinline__ uint32_t rotl32(uint32_t x, int r) {
    return (x << r) | (x >> (32 - r));
}

__device__ __forceinline__ uint32_t jax_bits_part(uint32_t n) {
    const uint32_t ks0 = 0u;
    const uint32_t ks1 = 42u;
    const uint32_t ks2 = 0x1BD11BDAu ^ 0u ^ 42u;   // 0x1BD11BF0
    uint32_t x0 = 0u + ks0;
    uint32_t x1 = n  + ks1;
#define TF_RND(r) { x0 += x1; x1 = rotl32(x1, (r)); x1 ^= x0; }
    TF_RND(13) TF_RND(15) TF_RND(26) TF_RND(6)   x0 += ks1; x1 += ks2 + 1u;
    TF_RND(17) TF_RND(29) TF_RND(16) TF_RND(24)  x0 += ks2; x1 += ks0 + 2u;
    TF_RND(13) TF_RND(15) TF_RND(26) TF_RND(6)   x0 += ks0; x1 += ks1 + 3u;
    TF_RND(17) TF_RND(29) TF_RND(16) TF_RND(24)  x0 += ks1; x1 += ks2 + 4u;
    TF_RND(13) TF_RND(15) TF_RND(26) TF_RND(6)   x0 += ks2; x1 += ks0 + 5u;
#undef TF_RND
    return x0 ^ x1;
}

__device__ __forceinline__ float jax_gumbel(uint32_t n) {
    const float TINY = 1.17549435e-38f;
    uint32_t bits = jax_bits_part(n);
    float u01 = __uint_as_float((bits >> 9) | 0x3f800000u) - 1.0f;
    float u = fmaxf(TINY, u01 + TINY);
    return -logf(-logf(u));
}

__device__ __forceinline__ uint32_t f2s(float f) {
    uint32_t u = __float_as_uint(f);
    return u ^ (uint32_t)(((int32_t)u >> 31) | (int32_t)0x80000000);
}

// ---------------------------------------------------------------------------
// PTX helpers (bulk-copy pipeline + L2 cache-hint policies)
// ---------------------------------------------------------------------------
__device__ __forceinline__ uint32_t smem_u32(const void* p) {
    uint32_t a;
    asm("{ .reg .u64 t; cvta.to.shared.u64 t, %1; cvt.u32.u64 %0, t; }"
        : "=r"(a) : "l"(p));
    return a;
}

__device__ __forceinline__ uint64_t policy_evict_last() {
    uint64_t pol;
    asm("createpolicy.fractional.L2::evict_last.b64 %0, 1.0;" : "=l"(pol));
    return pol;
}

__device__ __forceinline__ uint64_t policy_evict_first() {
    uint64_t pol;
    asm("createpolicy.fractional.L2::evict_first.b64 %0, 1.0;" : "=l"(pol));
    return pol;
}

__device__ __forceinline__ void mbar_init(uint32_t mbar, uint32_t count) {
    asm volatile("mbarrier.init.shared.b64 [%0], %1;" :: "r"(mbar), "r"(count)
                 : "memory");
}

__device__ __forceinline__ void mbar_expect_tx(uint32_t mbar, uint32_t bytes) {
    asm volatile("mbarrier.arrive.expect_tx.shared.b64 _, [%0], %1;"
                 :: "r"(mbar), "r"(bytes) : "memory");
}

__device__ __forceinline__ void bulk_g2s_pol(uint32_t smem_dst,
                                             const void* gmem_src,
                                             uint32_t bytes, uint32_t mbar,
                                             uint64_t pol) {
    asm volatile(
        "cp.async.bulk.shared::cta.global.mbarrier::complete_tx::bytes"
        ".L2::cache_hint [%0], [%1], %2, [%3], %4;"
        :: "r"(smem_dst), "l"(gmem_src), "r"(bytes), "r"(mbar), "l"(pol)
        : "memory");
}

__device__ __forceinline__ void mbar_wait(uint32_t mbar, uint32_t parity) {
    asm volatile(
        "{\n\t"
        ".reg .pred P;\n\t"
        "WAIT_%=:\n\t"
        "mbarrier.try_wait.parity.acquire.cta.shared::cta.b64 P, [%0], %1, 0x989680;\n\t"
        "@P bra.uni DONE_%=;\n\t"
        "bra.uni WAIT_%=;\n\t"
        "DONE_%=:\n\t"
        "}"
        :: "r"(mbar), "r"(parity) : "memory");
}

// Fill buffer b with tile t: one expect_tx, NSUB parallel bulk copies.
__device__ __forceinline__ void fill_tile(uint32_t smem_base, const char* gsrc,
                                          uint32_t mbar0, int b, int t,
                                          uint64_t pol_last, uint64_t pol_first) {
    uint32_t mbar = mbar0 + 8 * b;
    uint64_t pol = (t < PERSIST_NT) ? pol_last : pol_first;
    mbar_expect_tx(mbar, TILE_BYTES);
    #pragma unroll
    for (int s = 0; s < NSUB; ++s) {
        bulk_g2s_pol(smem_base + b * TILE_BYTES + s * SUB_BYTES,
                     gsrc + (size_t)t * TILE_BYTES + s * SUB_BYTES,
                     SUB_BYTES, mbar, pol);
    }
}

// ---------------------------------------------------------------------------
// One CTA (512 thr) per row. cp.async.bulk streams the row through a 4-deep
// smem tile ring with L2 hints; threads scan landed tiles from smem and
// append candidates to a smem list; selection + gumbel sampling in-place.
// ---------------------------------------------------------------------------
__global__ __launch_bounds__(NTH)
void sampler_l2pin512_kernel(const float* __restrict__ logits,
                             const float* __restrict__ temps,
                             float*       __restrict__ out)
{
    extern __shared__ __align__(1024) char smem[];
    __shared__ float s_val[CAP];
    __shared__ int   s_idx[CAP];
    __shared__ int   s_cnt;
    __shared__ float s_kth;
    __shared__ unsigned long long s_best;

    const int row = blockIdx.x;
    const int tid = threadIdx.x;
    const int k   = KTOP;
    const float temp = temps[row];
    const char* __restrict__ gsrc =
        reinterpret_cast<const char*>(logits) + (size_t)row * ROW_BYTES;

    const uint32_t smem_base = smem_u32(smem);
    const uint32_t mbar0     = smem_base + MBAR_OFF;
    const uint64_t pol_last  = policy_evict_last();
    const uint64_t pol_first = policy_evict_first();

    if (tid == 0) {
        s_cnt = 0; s_best = 0ull; s_kth = __int_as_float(0xFF800000);
        #pragma unroll
        for (int b = 0; b < NBUF; ++b) mbar_init(mbar0 + 8 * b, 1);
    }
    __syncthreads();

    // Prime the pipeline: tiles 0..NBUF-1.
    if (tid == 0) {
        #pragma unroll
        for (int b = 0; b < NBUF; ++b)
            fill_tile(smem_base, gsrc, mbar0, b, b, pol_last, pol_first);
    }

    // ---------------- streaming scan ----------------
    for (int t = 0; t < NT; ++t) {
        const int b = t % NBUF;
        mbar_wait(mbar0 + 8 * b, (t / NBUF) & 1);

        const float4* __restrict__ tb =
            reinterpret_cast<const float4*>(smem + b * TILE_BYTES);
        #pragma unroll 2
        for (int i = tid; i < TILE_F4; i += NTH) {
            float4 v = tb[i];
            float m = fmaxf(fmaxf(v.x, v.y), fmaxf(v.z, v.w));
            if (m >= THRESH) {     // rare (~0.5% of float4 groups)
                float xs[4] = {v.x, v.y, v.z, v.w};
                #pragma unroll
                for (int e = 0; e < 4; ++e) {
                    if (xs[e] >= THRESH) {
                        int p = atomicAdd(&s_cnt, 1);
                        if (p < CAP) {
                            s_val[p] = xs[e];
                            s_idx[p] = t * TILE_F + i * 4 + e;
                        }
                    }
                }
            }
        }
        __syncthreads();           // whole CTA done reading buffer b

        const int nt2 = t + NBUF;  // refill this buffer with a later tile
        if (nt2 < NT && tid == 0)
            fill_tile(smem_base, gsrc, mbar0, b, nt2, pol_last, pol_first);
    }

    int cnt = s_cnt;

    // ---------------- fallback (never taken for this input) ----------------
    if (cnt < k || cnt > CAP) {
        const float4* __restrict__ rowp =
            reinterpret_cast<const float4*>(logits + (size_t)row * VV);
        float Tlo = -3.0e38f, Thi = 3.0e38f, T = THRESH;
        int c = cnt;
        for (int attempt = 0; attempt < 48; ++attempt) {
            if (c < k) { Thi = T; T = (Tlo < -1.0e38f) ? (T - 2.0f) : 0.5f * (Tlo + Thi); }
            else       { Tlo = T; T = (Thi >  1.0e38f) ? (T + 2.0f) : 0.5f * (Tlo + Thi); }
            __syncthreads();
            if (tid == 0) s_cnt = 0;
            __syncthreads();
            for (int i = tid; i < VV / 4; i += NTH) {
                float4 w = rowp[i];
                float m = fmaxf(fmaxf(w.x, w.y), fmaxf(w.z, w.w));
                if (m >= T) {
                    float xs[4] = {w.x, w.y, w.z, w.w};
                    #pragma unroll
                    for (int e = 0; e < 4; ++e) {
                        if (xs[e] >= T) {
                            int p = atomicAdd(&s_cnt, 1);
                            if (p < CAP) { s_val[p] = xs[e]; s_idx[p] = i * 4 + e; }
                        }
                    }
                }
            }
            __syncthreads();
            c = s_cnt;
            if (c >= k && c <= CAP) break;
        }
        cnt = min(c, CAP);
    }

    // ---------------- selection + sampling ----------------
    // Exact temperature scaling (bit-matches reference's f32 division).
    for (int i = tid; i < cnt; i += NTH)
        s_val[i] = __fdiv_rn(s_val[i], temp);
    __syncthreads();

    // k-th largest among candidates (duplicate-aware rank count).
    for (int i = tid; i < cnt; i += NTH) {
        float vv = s_val[i];
        int cg = 0, ce = 0;
        for (int j = 0; j < cnt; ++j) {
            float u = s_val[j];
            cg += (u > vv);
            ce += (u == vv);
        }
        if (cg < k && cg + ce >= k) s_kth = vv;   // unique value; benign race
    }
    __syncthreads();
    float kv = s_kth;

    // Gumbel-perturbed argmax over {scaled >= kth}; first-index tie-break.
    for (int i = tid; i < cnt; i += NTH) {
        float vv = s_val[i];
        if (vv >= kv) {
            int col = s_idx[i];
            uint32_t n = (uint32_t)row * (uint32_t)VV + (uint32_t)col;
            float tot = vv + jax_gumbel(n);
            unsigned long long pack =
                ((unsigned long long)f2s(tot) << 32) |
                (unsigned long long)(0xFFFFFFFFu - (uint32_t)col);
            atomicMax(&s_best, pack);
        }
    }
    __syncthreads();

    if (tid == 0) {
        int win = (int)(0xFFFFFFFFu - (uint32_t)(s_best & 0xFFFFFFFFull));
        out[row] = (float)win;   // harness output dtype is float32
    }
}

extern "C" void kernel_launch(void* const* d_in, const int* in_sizes, int n_in,
                              void* d_out, int out_size)
{
    const float* logits = (const float*)d_in[0];
    const float* temps  = (const float*)d_in[1];
    float* out = (float*)d_out;

    int rows = (n_in >= 2 && in_sizes[1] > 0) ? in_sizes[1] : ROWS_MAX;  // 256

    cudaFuncSetAttribute(sampler_l2pin512_kernel,
                         cudaFuncAttributeMaxDynamicSharedMemorySize, SMEM_TOTAL);
    sampler_l2pin512_kernel<<<rows, NTH, SMEM_TOTAL>>>(logits, temps, out);
}